// round 1
// baseline (speedup 1.0000x reference)
#include <cuda_runtime.h>
#include <math.h>

// InfoNCE / NT-Xent loss, B=4096, D=128, n=8192, T=0.1
//
// loss = mean_i [ LSE_i - pos_i ]
//   pos_i  = sim[i, i^4096]
//   LSE_i  = log( exp(pos_i) + sum_{j != i} exp(sim[i,j]) )
//          (positive appears twice: once as logits[:,0], once among negatives)
//
// Kernel 1: tiled fp32 GEMM (z z^T / T) with online row-wise (max,sumexp),
//           column-split into 16 partials per row.
// Kernel 2: merge partials per row -> LSE - pos, block-reduce, atomicAdd(double).
// Kernel 3: finalize mean.

#define N_TOT  8192
#define B_HALF 4096
#define DDIM   128
#define SCALE  10.0f      // 1/T

#define BM 128
#define BN 128
#define SPLITS 16
#define COLS_PER_SPLIT 512
#define TILES_PER_SPLIT 4
#define THREADS 256

// smem: As float[128][132] (row-major, pad 4) + Bs float[128][129] (k-major, pad 1)
#define AS_STRIDE 132
#define BS_STRIDE 129
#define SMEM_FLOATS (BM * AS_STRIDE + DDIM * BS_STRIDE)
#define SMEM_BYTES  (SMEM_FLOATS * 4)

__device__ float  g_pm[SPLITS * N_TOT];
__device__ float  g_ps[SPLITS * N_TOT];
__device__ float  g_pp[SPLITS * N_TOT];
__device__ double g_acc;

__global__ void infonce_zero_kernel() { g_acc = 0.0; }

__global__ __launch_bounds__(THREADS, 1)
void infonce_main_kernel(const float* __restrict__ zi, const float* __restrict__ zj)
{
    extern __shared__ float smem[];
    float* As = smem;                        // [BM][AS_STRIDE]
    float* Bs = smem + BM * AS_STRIDE;       // [DDIM][BS_STRIDE], k-major

    const int tid = threadIdx.x;
    const int tx  = tid & 15;                // column lane (16)
    const int ty  = tid >> 4;                // row lane (16)
    const int r0  = blockIdx.x * BM;
    const int c_split0 = blockIdx.y * COLS_PER_SPLIT;

    // ---- load A rows [r0, r0+128) into smem (row-major, float4, conflict-free)
    {
        const float4* s4 = (r0 < B_HALF)
            ? (const float4*)(zi + (size_t)r0 * DDIM)
            : (const float4*)(zj + (size_t)(r0 - B_HALF) * DDIM);
        float4* As4 = (float4*)As;           // row stride = 33 float4 (=132 floats)
        #pragma unroll
        for (int it = 0; it < 16; it++) {
            int fid = tid + it * THREADS;    // 0..4095
            int row = fid >> 5;
            int k4  = fid & 31;
            As4[row * 33 + k4] = s4[row * 32 + k4];
        }
    }

    // per-thread online softmax state for 8 rows: rows = r0 + ty + 16*i
    float m[8], s[8], pv[8];
    #pragma unroll
    for (int i = 0; i < 8; i++) { m[i] = -INFINITY; s[i] = 0.0f; pv[i] = 0.0f; }

    for (int t = 0; t < TILES_PER_SPLIT; t++) {
        const int c0 = c_split0 + t * BN;

        __syncthreads();  // previous tile's Bs reads done / As ready (t==0)

        // ---- load B tile (global rows c0..c0+127) transposed into k-major Bs
        {
            const float4* s4 = (c0 < B_HALF)
                ? (const float4*)(zi + (size_t)c0 * DDIM)
                : (const float4*)(zj + (size_t)(c0 - B_HALF) * DDIM);
            #pragma unroll
            for (int it = 0; it < 16; it++) {
                int fid = tid + it * THREADS;
                int col = fid >> 5;          // local column (0..127)
                int k4  = fid & 31;
                float4 v = s4[col * 32 + k4];
                int kb = k4 * 4;
                Bs[(kb + 0) * BS_STRIDE + col] = v.x;
                Bs[(kb + 1) * BS_STRIDE + col] = v.y;
                Bs[(kb + 2) * BS_STRIDE + col] = v.z;
                Bs[(kb + 3) * BS_STRIDE + col] = v.w;
            }
        }
        __syncthreads();

        // ---- 128x128 tile GEMM: acc[i][j] = dot(row ty+16i, col tx+16j)
        float acc[8][8];
        #pragma unroll
        for (int i = 0; i < 8; i++)
            #pragma unroll
            for (int j = 0; j < 8; j++)
                acc[i][j] = 0.0f;

        #pragma unroll 2
        for (int k = 0; k < DDIM; k++) {
            float a[8], b[8];
            #pragma unroll
            for (int i = 0; i < 8; i++)
                a[i] = As[(ty + 16 * i) * AS_STRIDE + k];      // broadcast
            #pragma unroll
            for (int j = 0; j < 8; j++)
                b[j] = Bs[k * BS_STRIDE + tx + 16 * j];        // lane-stride 1
            #pragma unroll
            for (int i = 0; i < 8; i++)
                #pragma unroll
                for (int j = 0; j < 8; j++)
                    acc[i][j] = fmaf(a[i], b[j], acc[i][j]);
        }

        // ---- online logsumexp epilogue (weight 0 on diag, weight 2 on positive)
        #pragma unroll
        for (int i = 0; i < 8; i++) {
            const int row = r0 + ty + 16 * i;
            const int pc  = row ^ B_HALF;
            float tm = -INFINITY;
            #pragma unroll
            for (int j = 0; j < 8; j++) {
                int col = c0 + tx + 16 * j;
                float v = acc[i][j] * SCALE;
                tm = fmaxf(tm, (col == row) ? -INFINITY : v);
            }
            float mn   = fmaxf(m[i], tm);
            float ssum = s[i] * __expf(m[i] - mn);
            #pragma unroll
            for (int j = 0; j < 8; j++) {
                int col = c0 + tx + 16 * j;
                float v = acc[i][j] * SCALE;
                if (col == row) continue;
                float e = __expf(v - mn);
                if (col == pc) { pv[i] = v; e += e; }  // positive counted twice
                ssum += e;
            }
            m[i] = mn;
            s[i] = ssum;
        }
    }

    // ---- reduce 16 column-lanes (tx) per row via shuffles, write partials
    #pragma unroll
    for (int i = 0; i < 8; i++) {
        #pragma unroll
        for (int off = 1; off < 16; off <<= 1) {
            float mo = __shfl_xor_sync(0xffffffffu, m[i],  off);
            float so = __shfl_xor_sync(0xffffffffu, s[i],  off);
            float po = __shfl_xor_sync(0xffffffffu, pv[i], off);
            float mn = fmaxf(m[i], mo);
            s[i]  = s[i] * __expf(m[i] - mn) + so * __expf(mo - mn);
            m[i]  = mn;
            pv[i] += po;
        }
        if (tx == 0) {
            int row = r0 + ty + 16 * i;
            int idx = blockIdx.y * N_TOT + row;
            g_pm[idx] = m[i];
            g_ps[idx] = s[i];
            g_pp[idx] = pv[i];
        }
    }
}

__global__ void infonce_reduce_kernel()
{
    const int row = blockIdx.x * 256 + threadIdx.x;   // 32 blocks x 256 = 8192

    float M = -INFINITY;
    #pragma unroll
    for (int k = 0; k < SPLITS; k++)
        M = fmaxf(M, g_pm[k * N_TOT + row]);
    float S = 0.0f, P = 0.0f;
    #pragma unroll
    for (int k = 0; k < SPLITS; k++) {
        S += g_ps[k * N_TOT + row] * __expf(g_pm[k * N_TOT + row] - M);
        P += g_pp[k * N_TOT + row];
    }
    float val = M + logf(S) - P;   // LSE_row - pos_row

    __shared__ float red[256];
    red[threadIdx.x] = val;
    __syncthreads();
    #pragma unroll
    for (int off = 128; off > 0; off >>= 1) {
        if (threadIdx.x < off) red[threadIdx.x] += red[threadIdx.x + off];
        __syncthreads();
    }
    if (threadIdx.x == 0) atomicAdd(&g_acc, (double)red[0]);
}

__global__ void infonce_finalize_kernel(float* out)
{
    out[0] = (float)(g_acc / (double)N_TOT);
}

extern "C" void kernel_launch(void* const* d_in, const int* in_sizes, int n_in,
                              void* d_out, int out_size)
{
    const float* zi = (const float*)d_in[0];
    const float* zj = (const float*)d_in[1];
    float* out = (float*)d_out;

    cudaFuncSetAttribute(infonce_main_kernel,
                         cudaFuncAttributeMaxDynamicSharedMemorySize, SMEM_BYTES);

    infonce_zero_kernel<<<1, 1>>>();
    dim3 grid(N_TOT / BM, SPLITS);   // (64, 16) = 1024 blocks
    infonce_main_kernel<<<grid, THREADS, SMEM_BYTES>>>(zi, zj);
    infonce_reduce_kernel<<<32, 256>>>();
    infonce_finalize_kernel<<<1, 1>>>(out);
}

// round 4
// speedup vs baseline: 3.5056x; 3.5056x over previous
#include <cuda_runtime.h>
#include <cstdint>
#include <math.h>

// ============================================================================
// InfoNCE / NT-Xent loss via mma.sync tf32 (base sm_103 target — no 'a' ptxas).
//   loss = mean_i [ LSE_i - pos_i ],  pos_i = sim[i, i^4096]
//   LSE_i = log( 2*exp(pos_i) + sum_{j != i,pos} exp(sim[i,j]) )
// sim = Z Z^T / T, Z = concat(zi,zj) [8192x128] fp32. Log2-domain softmax.
// Main kernel: grid (64 row-blocks, 16 col-splits), 256 thr, 8 warps,
//   warp tile 64x32, CTA tile 128x128, K=128, cp.async double-buffered B.
// The positive's "second copy" (logits[:,0]) is added in the reduce kernel.
// ============================================================================

#define N_TOT   8192
#define B_HALF  4096
#define DDIM    128
#define TILE    128
#define SPLITS  16
#define TILES_PER_SPLIT 4
#define THREADS 256

#define C_L2E   14.4269504088896340736f   // (1/T)*log2(e) = 10*log2(e)
#define LN2     0.69314718055994530942

// smem: As[128][132] fp32 + 2x Bs[128][132] fp32
#define LDF       132                      // padded row stride (floats)
#define LDB       528                      // row stride bytes
#define TILE_BYTES (TILE * LDB)            // 67584
#define SM_A      0
#define SM_B0     TILE_BYTES
#define SM_B1     (2 * TILE_BYTES)
#define SMEM_BYTES (3 * TILE_BYTES)        // 202752

__device__ float g_pm[SPLITS * N_TOT];
__device__ float g_ps[SPLITS * N_TOT];
__device__ float g_pp[SPLITS * N_TOT];

// ---------------------------------------------------------------------------
__device__ __forceinline__ uint32_t smem_u32(const void* p) {
    uint32_t a;
    asm("{ .reg .u64 t; cvta.to.shared.u64 t, %1; cvt.u32.u64 %0, t; }"
        : "=r"(a) : "l"(p));
    return a;
}
__device__ __forceinline__ float ex2f(float x) {
    float y; asm("ex2.approx.ftz.f32 %0, %1;" : "=f"(y) : "f"(x)); return y;
}
__device__ __forceinline__ void cp16(uint32_t dst, const void* src) {
    asm volatile("cp.async.cg.shared.global [%0], [%1], 16;"
                 :: "r"(dst), "l"(src));
}
#define CP_COMMIT() asm volatile("cp.async.commit_group;" ::: "memory")
template <int N>
__device__ __forceinline__ void cp_wait() {
    asm volatile("cp.async.wait_group %0;" :: "n"(N) : "memory");
}
__device__ __forceinline__ void mma8(float& d0, float& d1, float& d2, float& d3,
                                     uint32_t a0, uint32_t a1, uint32_t a2, uint32_t a3,
                                     uint32_t b0, uint32_t b1) {
    asm volatile(
        "mma.sync.aligned.m16n8k8.row.col.f32.tf32.tf32.f32 "
        "{%0,%1,%2,%3}, {%4,%5,%6,%7}, {%8,%9}, {%0,%1,%2,%3};"
        : "+f"(d0), "+f"(d1), "+f"(d2), "+f"(d3)
        : "r"(a0), "r"(a1), "r"(a2), "r"(a3), "r"(b0), "r"(b1));
}

__device__ __forceinline__ const float* zrow(const float* zi, const float* zj, int g) {
    return (g < B_HALF) ? (zi + (size_t)g * DDIM) : (zj + (size_t)(g - B_HALF) * DDIM);
}

// load a 128-row x 128-float tile into smem via cp.async (16B chunks)
__device__ __forceinline__ void load_tile(uint32_t sdst, const float* src, int tid) {
    #pragma unroll
    for (int it = 0; it < 16; it++) {
        int c = tid + it * THREADS;      // 0..4095
        int row = c >> 5, q = c & 31;    // 32 x 16B per row
        cp16(sdst + row * LDB + q * 16, (const char*)src + row * 512 + q * 16);
    }
}

// ---------------------------------------------------------------------------
__global__ __launch_bounds__(THREADS, 1)
void infonce_mma_kernel(const float* __restrict__ zi, const float* __restrict__ zj)
{
    extern __shared__ char smem[];
    const uint32_t sb = smem_u32(smem);
    const int tid = threadIdx.x, lane = tid & 31, wid = tid >> 5;
    const int g = lane >> 2, tg = lane & 3;       // mma group / thread-in-group
    const int warpRow = wid >> 2, warpCol = wid & 3;
    const int r0 = blockIdx.x * TILE;
    const int csplit = blockIdx.y * (TILE * TILES_PER_SPLIT);

    float* As = (float*)smem;
    float* Bsbuf[2] = { (float*)(smem + SM_B0), (float*)(smem + SM_B1) };

    // ---- prologue: A tile + B0 (group0), B1 (group1)
    load_tile(sb + SM_A,  zrow(zi, zj, r0), tid);
    load_tile(sb + SM_B0, zrow(zi, zj, csplit), tid);
    CP_COMMIT();
    load_tile(sb + SM_B1, zrow(zi, zj, csplit + TILE), tid);
    CP_COMMIT();

    // per-thread LSE state: 8 rows (i*2+h), row = r0+warpRow*64+i*16+h*8+g
    float m[8], s[8], pv[8];
    #pragma unroll
    for (int r = 0; r < 8; r++) { m[r] = -1e30f; s[r] = 0.0f; pv[r] = 0.0f; }

    const int R0 = warpRow * 64;
    const int C0w = warpCol * 32;

    #pragma unroll
    for (int t = 0; t < TILES_PER_SPLIT; t++) {
        if (t < 3) cp_wait<1>(); else cp_wait<0>();
        __syncthreads();
        const float* Bs = Bsbuf[t & 1];

        float acc[4][4][4];
        #pragma unroll
        for (int i = 0; i < 4; i++)
            #pragma unroll
            for (int j = 0; j < 4; j++)
                #pragma unroll
                for (int q = 0; q < 4; q++) acc[i][j][q] = 0.0f;

        #pragma unroll 4
        for (int ks = 0; ks < 16; ks++) {
            const int k0 = ks * 8;
            uint32_t A0[4], A1[4], A2[4], A3[4];
            #pragma unroll
            for (int i = 0; i < 4; i++) {
                const float* ap = As + (R0 + i * 16 + g) * LDF + k0 + tg;
                A0[i] = __float_as_uint(ap[0]);
                A2[i] = __float_as_uint(ap[4]);
                A1[i] = __float_as_uint(ap[8 * LDF]);
                A3[i] = __float_as_uint(ap[8 * LDF + 4]);
            }
            uint32_t B0r[4], B1r[4];
            #pragma unroll
            for (int j = 0; j < 4; j++) {
                const float* bp = Bs + (C0w + j * 8 + g) * LDF + k0 + tg;
                B0r[j] = __float_as_uint(bp[0]);
                B1r[j] = __float_as_uint(bp[4]);
            }
            #pragma unroll
            for (int i = 0; i < 4; i++)
                #pragma unroll
                for (int j = 0; j < 4; j++)
                    mma8(acc[i][j][0], acc[i][j][1], acc[i][j][2], acc[i][j][3],
                         A0[i], A1[i], A2[i], A3[i], B0r[j], B1r[j]);
        }

        // ---- fused online LSE epilogue (log2 domain)
        const int tileC0 = csplit + t * TILE + C0w;
        #pragma unroll
        for (int i = 0; i < 4; i++) {
            #pragma unroll
            for (int h = 0; h < 2; h++) {
                const int ri = i * 2 + h;
                const int rowg = r0 + R0 + i * 16 + h * 8 + g;
                const int prow = rowg ^ B_HALF;
                float f[8], rmax = -1e30f;
                #pragma unroll
                for (int j = 0; j < 4; j++) {
                    #pragma unroll
                    for (int q = 0; q < 2; q++) {
                        const int colg = tileC0 + j * 8 + tg * 2 + q;
                        float v = acc[i][j][h * 2 + q] * C_L2E;
                        if (colg == rowg) v = -1e30f;    // exclude diagonal
                        if (colg == prow) pv[ri] = v;    // record positive
                        f[j * 2 + q] = v;
                        rmax = fmaxf(rmax, v);
                    }
                }
                if (rmax > m[ri] - 27.0f) {
                    const float mn = fmaxf(m[ri], rmax);
                    float acc_s = s[ri] * ex2f(m[ri] - mn);
                    #pragma unroll
                    for (int x = 0; x < 8; x++) acc_s += ex2f(f[x] - mn);
                    m[ri] = mn; s[ri] = acc_s;
                }
            }
        }

        if (t < 2) {
            __syncthreads();   // all warps done reading Bs[t&1]
            load_tile(t & 1 ? sb + SM_B1 : sb + SM_B0,
                      zrow(zi, zj, csplit + (t + 2) * TILE), tid);
            CP_COMMIT();
        }
    }

    // ---- lane reduction: lanes sharing rows differ only in tg (lane&3)
    #pragma unroll
    for (int ri = 0; ri < 8; ri++) {
        #pragma unroll
        for (int off = 1; off < 4; off <<= 1) {
            float mo = __shfl_xor_sync(0xffffffffu, m[ri],  off);
            float so = __shfl_xor_sync(0xffffffffu, s[ri],  off);
            float po = __shfl_xor_sync(0xffffffffu, pv[ri], off);
            float mn = fmaxf(m[ri], mo);
            s[ri]  = s[ri] * ex2f(m[ri] - mn) + so * ex2f(mo - mn);
            m[ri]  = mn;
            pv[ri] += po;
        }
    }

    // ---- CTA reduction across the 4 warp-columns via smem (alias B0 area)
    __syncthreads();
    float* redm = (float*)(smem + SM_B0);
    float* reds = redm + 512;
    float* redp = redm + 1024;
    if (tg == 0) {
        #pragma unroll
        for (int ri = 0; ri < 8; ri++) {
            const int rl = R0 + (ri >> 1) * 16 + (ri & 1) * 8 + g;
            redm[rl * 4 + warpCol] = m[ri];
            reds[rl * 4 + warpCol] = s[ri];
            redp[rl * 4 + warpCol] = pv[ri];
        }
    }
    __syncthreads();
    if (tid < TILE) {
        float M = -1e30f;
        #pragma unroll
        for (int w = 0; w < 4; w++) M = fmaxf(M, redm[tid * 4 + w]);
        float S = 0.0f, P = 0.0f;
        #pragma unroll
        for (int w = 0; w < 4; w++) {
            S += reds[tid * 4 + w] * ex2f(redm[tid * 4 + w] - M);
            P += redp[tid * 4 + w];
        }
        const int idx = blockIdx.y * N_TOT + r0 + tid;
        g_pm[idx] = M; g_ps[idx] = S; g_pp[idx] = P;
    }
}

// ---------------------------------------------------------------------------
// merge splits per row, add the positive's second copy, mean, write out
// ---------------------------------------------------------------------------
__global__ void infonce_reduce_final(float* out)
{
    const int t = threadIdx.x;   // 1024 threads
    double acc = 0.0;
    for (int r = t; r < N_TOT; r += 1024) {
        float M = -1e30f;
        #pragma unroll
        for (int k = 0; k < SPLITS; k++) M = fmaxf(M, g_pm[k * N_TOT + r]);
        float S = 0.0f, P = 0.0f;
        #pragma unroll
        for (int k = 0; k < SPLITS; k++) {
            S += g_ps[k * N_TOT + r] * exp2f(g_pm[k * N_TOT + r] - M);
            P += g_pp[k * N_TOT + r];
        }
        S += exp2f(P - M);                 // logits[:,0] copy of the positive
        acc += (double)(M + log2f(S) - P); // row LSE - pos, in log2 units
    }
    __shared__ double red[1024];
    red[t] = acc;
    __syncthreads();
    #pragma unroll
    for (int off = 512; off > 0; off >>= 1) {
        if (t < off) red[t] += red[t + off];
        __syncthreads();
    }
    if (t == 0) out[0] = (float)(red[0] * LN2 / (double)N_TOT);
}

// ---------------------------------------------------------------------------
extern "C" void kernel_launch(void* const* d_in, const int* in_sizes, int n_in,
                              void* d_out, int out_size)
{
    const float* zi = (const float*)d_in[0];
    const float* zj = (const float*)d_in[1];
    float* out = (float*)d_out;

    static bool attr_set = false;
    if (!attr_set) {
        cudaFuncSetAttribute(infonce_mma_kernel,
                             cudaFuncAttributeMaxDynamicSharedMemorySize, SMEM_BYTES);
        attr_set = true;
    }

    dim3 grid(N_TOT / TILE, SPLITS);   // (64, 16)
    infonce_mma_kernel<<<grid, THREADS, SMEM_BYTES>>>(zi, zj);
    infonce_reduce_final<<<1, 1024>>>(out);
}

// round 5
// speedup vs baseline: 4.6854x; 1.3366x over previous
#include <cuda_runtime.h>
#include <cstdint>
#include <math.h>

// ============================================================================
// InfoNCE / NT-Xent loss via mma.sync tf32, exploiting sim = sim^T.
// Only upper-triangular 128x128 tiles are computed (2080 of 4096).
// Tile (I,J), J>I contributes row-LSE partials for block I rows AND
// column-LSE partials for block J rows. Partials land in 80 slots/row:
//   slot 0..15  : row-strip partials (strip chunk index m)
//   slot 16+I   : column partials from tile (I,J) for rows of block J
// Log2-domain softmax; positive's logits[:,0] copy added in the reducer.
// ============================================================================

#define N_TOT   8192
#define B_HALF  4096
#define DDIM    128
#define TILE    128
#define THREADS 256
#define SLOTS   80
#define NBLOCKS 544        // sum over I of (16 - I/4)

#define C_L2E   14.4269504088896340736f   // (1/T)*log2(e)
#define LN2     0.69314718055994530942

#define LDF       132
#define LDB       528
#define TILE_BYTES (TILE * LDB)            // 67584
#define SM_A      0
#define SM_B0     TILE_BYTES
#define SM_B1     (2 * TILE_BYTES)
#define SM_RED    (3 * TILE_BYTES)         // 2 KB transpose-reduce buffer
#define SMEM_BYTES (3 * TILE_BYTES + 2048) // 204800

__device__ float  g_pm[SLOTS * N_TOT];
__device__ float  g_ps[SLOTS * N_TOT];
__device__ float  g_pp[SLOTS * N_TOT];
__device__ double g_acc;

// ---------------------------------------------------------------------------
__device__ __forceinline__ uint32_t smem_u32(const void* p) {
    uint32_t a;
    asm("{ .reg .u64 t; cvta.to.shared.u64 t, %1; cvt.u32.u64 %0, t; }"
        : "=r"(a) : "l"(p));
    return a;
}
__device__ __forceinline__ float ex2f(float x) {
    float y; asm("ex2.approx.ftz.f32 %0, %1;" : "=f"(y) : "f"(x)); return y;
}
__device__ __forceinline__ void cp16(uint32_t dst, const void* src) {
    asm volatile("cp.async.cg.shared.global [%0], [%1], 16;" :: "r"(dst), "l"(src));
}
#define CP_COMMIT() asm volatile("cp.async.commit_group;" ::: "memory")
template <int N>
__device__ __forceinline__ void cp_wait() {
    asm volatile("cp.async.wait_group %0;" :: "n"(N) : "memory");
}
__device__ __forceinline__ void mma8(float& d0, float& d1, float& d2, float& d3,
                                     uint32_t a0, uint32_t a1, uint32_t a2, uint32_t a3,
                                     uint32_t b0, uint32_t b1) {
    asm volatile(
        "mma.sync.aligned.m16n8k8.row.col.f32.tf32.tf32.f32 "
        "{%0,%1,%2,%3}, {%4,%5,%6,%7}, {%8,%9}, {%0,%1,%2,%3};"
        : "+f"(d0), "+f"(d1), "+f"(d2), "+f"(d3)
        : "r"(a0), "r"(a1), "r"(a2), "r"(a3), "r"(b0), "r"(b1));
}
// select-based LSE merge: (m1,s1) <- merge((m1,s1),(m2,s2)); 1 EX2
__device__ __forceinline__ void lse_merge(float& m1, float& s1, float m2, float s2) {
    float mn = fmaxf(m1, m2), ml = fminf(m1, m2);
    float shi = (m1 >= m2) ? s1 : s2;
    float slo = (m1 >= m2) ? s2 : s1;
    s1 = shi + slo * ex2f(ml - mn);
    m1 = mn;
}
__device__ __forceinline__ const float* zrow(const float* zi, const float* zj, int g) {
    return (g < B_HALF) ? (zi + (size_t)g * DDIM) : (zj + (size_t)(g - B_HALF) * DDIM);
}
__device__ __forceinline__ void load_tile(uint32_t sdst, const float* src, int tid) {
    #pragma unroll
    for (int it = 0; it < 16; it++) {
        int c = tid + it * THREADS;
        int row = c >> 5, q = c & 31;
        cp16(sdst + row * LDB + q * 16, (const char*)src + row * 512 + q * 16);
    }
}

// ---------------------------------------------------------------------------
__global__ void infonce_init()
{
    const int i = blockIdx.x * blockDim.x + threadIdx.x;
    const int n = SLOTS * N_TOT;
    for (int k = i; k < n; k += gridDim.x * blockDim.x) {
        g_pm[k] = -1e30f; g_ps[k] = 0.0f; g_pp[k] = 0.0f;
    }
    if (i == 0) g_acc = 0.0;
}

// ---------------------------------------------------------------------------
__global__ __launch_bounds__(THREADS, 1)
void infonce_mma_kernel(const float* __restrict__ zi, const float* __restrict__ zj)
{
    extern __shared__ char smem[];
    const uint32_t sb = smem_u32(smem);
    const int tid = threadIdx.x, lane = tid & 31, wid = tid >> 5;
    const int g = lane >> 2, tg = lane & 3;
    const int warpRow = wid >> 2, warpCol = wid & 3;

    // bid -> (row block I, chunk m): chunks are aligned groups of 4 col-tiles
    int q = blockIdx.x, I = 0, cnt = 16;
    while (q >= cnt) { q -= cnt; I++; cnt = 16 - (I >> 2); }
    const int mchunk = (I >> 2) + q;
    const int Jstart = (I > 4 * mchunk) ? I : 4 * mchunk;
    const int L = 4 * mchunk + 4 - Jstart;           // 1..4 tiles
    const int r0 = I * TILE;

    float* As = (float*)smem;
    float* Bsbuf[2] = { (float*)(smem + SM_B0), (float*)(smem + SM_B1) };
    float* red = (float*)(smem + SM_RED);            // [128][3]

    // prologue
    load_tile(sb + SM_A,  zrow(zi, zj, r0), tid);
    load_tile(sb + SM_B0, zrow(zi, zj, Jstart * TILE), tid);
    CP_COMMIT();
    if (L > 1) load_tile(sb + SM_B1, zrow(zi, zj, (Jstart + 1) * TILE), tid);
    CP_COMMIT();

    const int R0 = warpRow * 64;
    const int C0w = warpCol * 32;
    const int rowBase = r0 + R0;

    float m[8], s[8], pv[8];
    #pragma unroll
    for (int r = 0; r < 8; r++) { m[r] = -1e30f; s[r] = 0.0f; pv[r] = 0.0f; }

    for (int t = 0; t < L; t++) {
        if (t < L - 1) cp_wait<1>(); else cp_wait<0>();
        __syncthreads();
        const float* Bs = Bsbuf[t & 1];
        const int J = Jstart + t;
        const int tileC0 = J * TILE + C0w;

        float acc[4][4][4];
        #pragma unroll
        for (int i = 0; i < 4; i++)
            #pragma unroll
            for (int j = 0; j < 4; j++)
                #pragma unroll
                for (int c = 0; c < 4; c++) acc[i][j][c] = 0.0f;

        #pragma unroll 4
        for (int ks = 0; ks < 16; ks++) {
            const int k0 = ks * 8;
            uint32_t A0[4], A1[4], A2[4], A3[4];
            #pragma unroll
            for (int i = 0; i < 4; i++) {
                const float* ap = As + (R0 + i * 16 + g) * LDF + k0 + tg;
                A0[i] = __float_as_uint(ap[0]);
                A2[i] = __float_as_uint(ap[4]);
                A1[i] = __float_as_uint(ap[8 * LDF]);
                A3[i] = __float_as_uint(ap[8 * LDF + 4]);
            }
            uint32_t B0r[4], B1r[4];
            #pragma unroll
            for (int j = 0; j < 4; j++) {
                const float* bp = Bs + (C0w + j * 8 + g) * LDF + k0 + tg;
                B0r[j] = __float_as_uint(bp[0]);
                B1r[j] = __float_as_uint(bp[4]);
            }
            #pragma unroll
            for (int i = 0; i < 4; i++)
                #pragma unroll
                for (int j = 0; j < 4; j++)
                    mma8(acc[i][j][0], acc[i][j][1], acc[i][j][2], acc[i][j][3],
                         A0[i], A1[i], A2[i], A3[i], B0r[j], B1r[j]);
        }

        // ---- row-wise online LSE (rows of block I)
        #pragma unroll
        for (int i = 0; i < 4; i++) {
            #pragma unroll
            for (int h = 0; h < 2; h++) {
                const int ri = i * 2 + h;
                const int rowg = rowBase + i * 16 + h * 8 + g;
                const int prow = rowg ^ B_HALF;
                float f[8], rmax = -1e30f;
                #pragma unroll
                for (int j = 0; j < 4; j++) {
                    #pragma unroll
                    for (int qq = 0; qq < 2; qq++) {
                        const int colg = tileC0 + j * 8 + tg * 2 + qq;
                        float v = acc[i][j][h * 2 + qq] * C_L2E;
                        if (colg == rowg) v = -1e30f;
                        if (colg == prow) pv[ri] = v;
                        f[j * 2 + qq] = v;
                        rmax = fmaxf(rmax, v);
                    }
                }
                if (rmax > m[ri] - 27.0f) {
                    const float mn = fmaxf(m[ri], rmax);
                    float acc_s = s[ri] * ex2f(m[ri] - mn);
                    #pragma unroll
                    for (int x = 0; x < 8; x++) acc_s += ex2f(f[x] - mn);
                    m[ri] = mn; s[ri] = acc_s;
                }
            }
        }

        // ---- column-wise LSE partials (rows of block J) for off-diag tiles
        if (J > I) {
            float tm[8], ts[8], tp[8];
            #pragma unroll
            for (int j = 0; j < 4; j++) {
                #pragma unroll
                for (int qq = 0; qq < 2; qq++) {
                    const int ci = j * 2 + qq;
                    const int colg = tileC0 + j * 8 + tg * 2 + qq;
                    const int target = colg ^ B_HALF;   // colg's positive row
                    float mx = -1e30f;
                    #pragma unroll
                    for (int i = 0; i < 4; i++)
                        mx = fmaxf(mx, fmaxf(acc[i][j][qq], acc[i][j][2 + qq]));
                    mx *= C_L2E;
                    float ssum = 0.0f, pvv = 0.0f;
                    #pragma unroll
                    for (int i = 0; i < 4; i++) {
                        #pragma unroll
                        for (int h = 0; h < 2; h++) {
                            const float v = acc[i][j][h * 2 + qq] * C_L2E;
                            const int rowg = rowBase + i * 16 + h * 8 + g;
                            if (rowg == target) pvv = v;
                            ssum += ex2f(v - mx);
                        }
                    }
                    tm[ci] = mx; ts[ci] = ssum; tp[ci] = pvv;
                }
            }
            // reduce across the 8 g-lanes sharing each column
            #pragma unroll
            for (int off = 4; off <= 16; off <<= 1) {
                #pragma unroll
                for (int ci = 0; ci < 8; ci++) {
                    float mo = __shfl_xor_sync(0xffffffffu, tm[ci], off);
                    float so = __shfl_xor_sync(0xffffffffu, ts[ci], off);
                    float po = __shfl_xor_sync(0xffffffffu, tp[ci], off);
                    lse_merge(tm[ci], ts[ci], mo, so);
                    tp[ci] += po;
                }
            }
            __syncthreads();   // (a) GEMM reads done; red buffer free
            if (warpRow == 1 && g == 0) {
                #pragma unroll
                for (int ci = 0; ci < 8; ci++) {
                    const int cl = C0w + (ci >> 1) * 8 + tg * 2 + (ci & 1);
                    red[cl * 3 + 0] = tm[ci];
                    red[cl * 3 + 1] = ts[ci];
                    red[cl * 3 + 2] = tp[ci];
                }
            }
            __syncthreads();   // (b)
            if (warpRow == 0 && g == 0) {
                const int slot = 16 + I;
                #pragma unroll
                for (int ci = 0; ci < 8; ci++) {
                    const int cl = C0w + (ci >> 1) * 8 + tg * 2 + (ci & 1);
                    lse_merge(tm[ci], ts[ci], red[cl * 3 + 0], red[cl * 3 + 1]);
                    tp[ci] += red[cl * 3 + 2];
                    const int gr = J * TILE + cl;
                    g_pm[slot * N_TOT + gr] = tm[ci];
                    g_ps[slot * N_TOT + gr] = ts[ci];
                    g_pp[slot * N_TOT + gr] = tp[ci];
                }
            }
        } else {
            __syncthreads();   // buffer free before refilling
        }

        if (t + 2 < L) {
            load_tile(t & 1 ? sb + SM_B1 : sb + SM_B0,
                      zrow(zi, zj, (J + 2) * TILE), tid);
            CP_COMMIT();
        }
    }

    // ---- row-partial writeout: reduce 4 tg-lanes, then 4 warpCols via smem
    #pragma unroll
    for (int ri = 0; ri < 8; ri++) {
        #pragma unroll
        for (int off = 1; off < 4; off <<= 1) {
            float mo = __shfl_xor_sync(0xffffffffu, m[ri],  off);
            float so = __shfl_xor_sync(0xffffffffu, s[ri],  off);
            float po = __shfl_xor_sync(0xffffffffu, pv[ri], off);
            lse_merge(m[ri], s[ri], mo, so);
            pv[ri] += po;
        }
    }
    __syncthreads();
    float* redm = (float*)(smem + SM_B0);
    float* reds = redm + 512;
    float* redp = redm + 1024;
    if (tg == 0) {
        #pragma unroll
        for (int ri = 0; ri < 8; ri++) {
            const int rl = R0 + (ri >> 1) * 16 + (ri & 1) * 8 + g;
            redm[rl * 4 + warpCol] = m[ri];
            reds[rl * 4 + warpCol] = s[ri];
            redp[rl * 4 + warpCol] = pv[ri];
        }
    }
    __syncthreads();
    if (tid < TILE) {
        float M = redm[tid * 4 + 0], S = reds[tid * 4 + 0], P = redp[tid * 4 + 0];
        #pragma unroll
        for (int w = 1; w < 4; w++) {
            lse_merge(M, S, redm[tid * 4 + w], reds[tid * 4 + w]);
            P += redp[tid * 4 + w];
        }
        const int idx = mchunk * N_TOT + r0 + tid;
        g_pm[idx] = M; g_ps[idx] = S; g_pp[idx] = P;
    }
}

// ---------------------------------------------------------------------------
__global__ void infonce_reduce()
{
    const int r = blockIdx.x * 256 + threadIdx.x;   // 32 blocks x 256 = 8192
    float M = -1e30f, S = 0.0f, P = 0.0f;
    #pragma unroll 8
    for (int k = 0; k < SLOTS; k++) {
        lse_merge(M, S, g_pm[k * N_TOT + r], g_ps[k * N_TOT + r]);
        P += g_pp[k * N_TOT + r];
    }
    S += ex2f(P - M);                  // positive's logits[:,0] copy
    float val = M + log2f(S) - P;      // row LSE - pos (log2 units)

    __shared__ double redd[256];
    redd[threadIdx.x] = (double)val;
    __syncthreads();
    #pragma unroll
    for (int off = 128; off > 0; off >>= 1) {
        if (threadIdx.x < off) redd[threadIdx.x] += redd[threadIdx.x + off];
        __syncthreads();
    }
    if (threadIdx.x == 0) atomicAdd(&g_acc, redd[0]);
}

__global__ void infonce_final(float* out)
{
    out[0] = (float)(g_acc * LN2 / (double)N_TOT);
}

// ---------------------------------------------------------------------------
extern "C" void kernel_launch(void* const* d_in, const int* in_sizes, int n_in,
                              void* d_out, int out_size)
{
    const float* zi = (const float*)d_in[0];
    const float* zj = (const float*)d_in[1];
    float* out = (float*)d_out;

    static bool attr_set = false;
    if (!attr_set) {
        cudaFuncSetAttribute(infonce_mma_kernel,
                             cudaFuncAttributeMaxDynamicSharedMemorySize, SMEM_BYTES);
        attr_set = true;
    }

    infonce_init<<<256, 256>>>();
    infonce_mma_kernel<<<NBLOCKS, THREADS, SMEM_BYTES>>>(zi, zj);
    infonce_reduce<<<32, 256>>>();
    infonce_final<<<1, 1>>>(out);
}

// round 6
// speedup vs baseline: 7.4511x; 1.5903x over previous
#include <cuda_runtime.h>
#include <cuda_bf16.h>
#include <cstdint>
#include <math.h>

// ============================================================================
// InfoNCE / NT-Xent loss via mma.sync bf16 m16n8k16 (RN-prerounded inputs),
// exploiting sim = sim^T: only upper-triangular 128x128 tiles (2080/4096).
// Tile (I,J), J>I contributes row-LSE partials for block I rows AND
// column-LSE partials for block J rows. Partial slots per row:
//   slot 0..15 : row-strip partials (chunk m)   slot 16+I : col partials
// Log2-domain softmax; positive's logits[:,0] copy added in the reducer.
// RN bf16 conversion removes truncation bias (tf32-truncate gave 7e-4 bias).
// ============================================================================

#define N_TOT   8192
#define B_HALF  4096
#define DDIM    128
#define TILE    128
#define THREADS 256
#define SLOTS   80
#define NBLOCKS 544        // sum over I of (16 - I/4)

#define C_L2E   14.4269504088896340736f   // (1/T)*log2(e)
#define LN2     0.69314718055994530942

// bf16 tile: 128 rows x 128 bf16, padded row stride 272 B (68 words: bank-exact)
#define LDB       272
#define LDW       68                       // words per row
#define TILE_BYTES (TILE * LDB)            // 34816
#define SM_A      0
#define SM_B0     TILE_BYTES
#define SM_B1     (2 * TILE_BYTES)
#define SM_RED    (3 * TILE_BYTES)         // 2 KB transpose-reduce buffer
#define SMEM_BYTES (3 * TILE_BYTES + 2048) // 106496 -> 2 CTAs/SM

__device__ __nv_bfloat162 Zbf[N_TOT * DDIM / 2];   // RN-rounded concat(zi,zj)
__device__ float  g_pm[SLOTS * N_TOT];
__device__ float  g_ps[SLOTS * N_TOT];
__device__ float  g_pp[SLOTS * N_TOT];
__device__ double g_acc;

// ---------------------------------------------------------------------------
__device__ __forceinline__ uint32_t smem_u32(const void* p) {
    uint32_t a;
    asm("{ .reg .u64 t; cvta.to.shared.u64 t, %1; cvt.u32.u64 %0, t; }"
        : "=r"(a) : "l"(p));
    return a;
}
__device__ __forceinline__ float ex2f(float x) {
    float y; asm("ex2.approx.ftz.f32 %0, %1;" : "=f"(y) : "f"(x)); return y;
}
__device__ __forceinline__ void cp16(uint32_t dst, const void* src) {
    asm volatile("cp.async.cg.shared.global [%0], [%1], 16;" :: "r"(dst), "l"(src));
}
#define CP_COMMIT() asm volatile("cp.async.commit_group;" ::: "memory")
template <int N>
__device__ __forceinline__ void cp_wait() {
    asm volatile("cp.async.wait_group %0;" :: "n"(N) : "memory");
}
__device__ __forceinline__ void mma16(float& d0, float& d1, float& d2, float& d3,
                                      uint32_t a0, uint32_t a1, uint32_t a2, uint32_t a3,
                                      uint32_t b0, uint32_t b1) {
    asm volatile(
        "mma.sync.aligned.m16n8k16.row.col.f32.bf16.bf16.f32 "
        "{%0,%1,%2,%3}, {%4,%5,%6,%7}, {%8,%9}, {%0,%1,%2,%3};"
        : "+f"(d0), "+f"(d1), "+f"(d2), "+f"(d3)
        : "r"(a0), "r"(a1), "r"(a2), "r"(a3), "r"(b0), "r"(b1));
}
// select-based LSE merge, 1 EX2
__device__ __forceinline__ void lse_merge(float& m1, float& s1, float m2, float s2) {
    float mn = fmaxf(m1, m2), ml = fminf(m1, m2);
    float shi = (m1 >= m2) ? s1 : s2;
    float slo = (m1 >= m2) ? s2 : s1;
    s1 = shi + slo * ex2f(ml - mn);
    m1 = mn;
}
// load 128-row x 256B bf16 tile via cp.async (8 x 16B per thread)
__device__ __forceinline__ void load_tile(uint32_t sdst, int gRow0, int tid) {
    const char* src = (const char*)Zbf + (size_t)gRow0 * 256;
    #pragma unroll
    for (int it = 0; it < 8; it++) {
        int c = tid + it * THREADS;      // 0..2047
        int row = c >> 4, q = c & 15;
        cp16(sdst + row * LDB + q * 16, src + row * 256 + q * 16);
    }
}

// ---------------------------------------------------------------------------
// prep: RN-convert zi||zj -> Zbf, init partial slots + g_acc
__global__ void infonce_prep(const float* __restrict__ zi,
                             const float* __restrict__ zj)
{
    const int i = blockIdx.x * 256 + threadIdx.x;   // 2048 blocks = 524288 thr
    {   // convert 2 floats -> 1 bf16x2
        const int e = i * 2;
        const float2 v = (e < B_HALF * DDIM)
            ? *(const float2*)(zi + e)
            : *(const float2*)(zj + (e - B_HALF * DDIM));
        Zbf[i] = __floats2bfloat162_rn(v.x, v.y);
    }
    const int n = SLOTS * N_TOT;
    for (int k = i; k < n; k += 2048 * 256) {
        g_pm[k] = -1e30f; g_ps[k] = 0.0f; g_pp[k] = 0.0f;
    }
    if (i == 0) g_acc = 0.0;
}

// ---------------------------------------------------------------------------
__global__ __launch_bounds__(THREADS, 2)
void infonce_mma_kernel()
{
    extern __shared__ char smem[];
    const uint32_t sb = smem_u32(smem);
    const int tid = threadIdx.x, lane = tid & 31, wid = tid >> 5;
    const int g = lane >> 2, tg = lane & 3;
    const int warpRow = wid >> 2, warpCol = wid & 3;

    // bid -> (row block I, chunk m): chunks = aligned groups of 4 col-tiles
    int q = blockIdx.x, I = 0, cnt = 16;
    while (q >= cnt) { q -= cnt; I++; cnt = 16 - (I >> 2); }
    const int mchunk = (I >> 2) + q;
    const int Jstart = (I > 4 * mchunk) ? I : 4 * mchunk;
    const int L = 4 * mchunk + 4 - Jstart;           // 1..4 tiles
    const int r0 = I * TILE;

    const uint32_t* Aw = (const uint32_t*)smem;
    const uint32_t* Bwbuf[2] = { (const uint32_t*)(smem + SM_B0),
                                 (const uint32_t*)(smem + SM_B1) };
    float* red = (float*)(smem + SM_RED);            // [128][3]

    load_tile(sb + SM_A,  r0, tid);
    load_tile(sb + SM_B0, Jstart * TILE, tid);
    CP_COMMIT();
    if (L > 1) load_tile(sb + SM_B1, (Jstart + 1) * TILE, tid);
    CP_COMMIT();

    const int R0 = warpRow * 64;
    const int C0w = warpCol * 32;
    const int rowBase = r0 + R0;

    float m[8], s[8], pv[8];
    #pragma unroll
    for (int r = 0; r < 8; r++) { m[r] = -1e30f; s[r] = 0.0f; pv[r] = 0.0f; }

    for (int t = 0; t < L; t++) {
        if (t < L - 1) cp_wait<1>(); else cp_wait<0>();
        __syncthreads();
        const uint32_t* Bw = Bwbuf[t & 1];
        const int J = Jstart + t;
        const int tileC0 = J * TILE + C0w;

        float acc[4][4][4];
        #pragma unroll
        for (int i = 0; i < 4; i++)
            #pragma unroll
            for (int j = 0; j < 4; j++)
                #pragma unroll
                for (int c = 0; c < 4; c++) acc[i][j][c] = 0.0f;

        #pragma unroll 4
        for (int ks = 0; ks < 8; ks++) {            // 16 k per step
            const int kw = ks * 8 + tg;             // word offset in row
            uint32_t A0[4], A1[4], A2[4], A3[4];
            #pragma unroll
            for (int i = 0; i < 4; i++) {
                const uint32_t* ap = Aw + (R0 + i * 16 + g) * LDW + kw;
                A0[i] = ap[0];
                A2[i] = ap[4];
                A1[i] = ap[8 * LDW];
                A3[i] = ap[8 * LDW + 4];
            }
            uint32_t B0r[4], B1r[4];
            #pragma unroll
            for (int j = 0; j < 4; j++) {
                const uint32_t* bp = Bw + (C0w + j * 8 + g) * LDW + kw;
                B0r[j] = bp[0];
                B1r[j] = bp[4];
            }
            #pragma unroll
            for (int i = 0; i < 4; i++)
                #pragma unroll
                for (int j = 0; j < 4; j++)
                    mma16(acc[i][j][0], acc[i][j][1], acc[i][j][2], acc[i][j][3],
                          A0[i], A1[i], A2[i], A3[i], B0r[j], B1r[j]);
        }

        // ---- row-wise online LSE (rows of block I)
        #pragma unroll
        for (int i = 0; i < 4; i++) {
            #pragma unroll
            for (int h = 0; h < 2; h++) {
                const int ri = i * 2 + h;
                const int rowg = rowBase + i * 16 + h * 8 + g;
                const int prow = rowg ^ B_HALF;
                float f[8], rmax = -1e30f;
                #pragma unroll
                for (int j = 0; j < 4; j++) {
                    #pragma unroll
                    for (int qq = 0; qq < 2; qq++) {
                        const int colg = tileC0 + j * 8 + tg * 2 + qq;
                        float v = acc[i][j][h * 2 + qq] * C_L2E;
                        if (colg == rowg) v = -1e30f;
                        if (colg == prow) pv[ri] = v;
                        f[j * 2 + qq] = v;
                        rmax = fmaxf(rmax, v);
                    }
                }
                if (rmax > m[ri] - 27.0f) {
                    const float mn = fmaxf(m[ri], rmax);
                    float acc_s = s[ri] * ex2f(m[ri] - mn);
                    #pragma unroll
                    for (int x = 0; x < 8; x++) acc_s += ex2f(f[x] - mn);
                    m[ri] = mn; s[ri] = acc_s;
                }
            }
        }

        // ---- column-wise LSE partials (rows of block J), off-diag tiles
        if (J > I) {
            float tm[8], ts[8], tp[8];
            #pragma unroll
            for (int j = 0; j < 4; j++) {
                #pragma unroll
                for (int qq = 0; qq < 2; qq++) {
                    const int ci = j * 2 + qq;
                    const int colg = tileC0 + j * 8 + tg * 2 + qq;
                    const int target = colg ^ B_HALF;
                    float mx = -1e30f;
                    #pragma unroll
                    for (int i = 0; i < 4; i++)
                        mx = fmaxf(mx, fmaxf(acc[i][j][qq], acc[i][j][2 + qq]));
                    mx *= C_L2E;
                    float ssum = 0.0f, pvv = 0.0f;
                    #pragma unroll
                    for (int i = 0; i < 4; i++) {
                        #pragma unroll
                        for (int h = 0; h < 2; h++) {
                            const float v = acc[i][j][h * 2 + qq] * C_L2E;
                            const int rowg = rowBase + i * 16 + h * 8 + g;
                            if (rowg == target) pvv = v;
                            ssum += ex2f(v - mx);
                        }
                    }
                    tm[ci] = mx; ts[ci] = ssum; tp[ci] = pvv;
                }
            }
            #pragma unroll
            for (int off = 4; off <= 16; off <<= 1) {
                #pragma unroll
                for (int ci = 0; ci < 8; ci++) {
                    float mo = __shfl_xor_sync(0xffffffffu, tm[ci], off);
                    float so = __shfl_xor_sync(0xffffffffu, ts[ci], off);
                    float po = __shfl_xor_sync(0xffffffffu, tp[ci], off);
                    lse_merge(tm[ci], ts[ci], mo, so);
                    tp[ci] += po;
                }
            }
            __syncthreads();
            if (warpRow == 1 && g == 0) {
                #pragma unroll
                for (int ci = 0; ci < 8; ci++) {
                    const int cl = C0w + (ci >> 1) * 8 + tg * 2 + (ci & 1);
                    red[cl * 3 + 0] = tm[ci];
                    red[cl * 3 + 1] = ts[ci];
                    red[cl * 3 + 2] = tp[ci];
                }
            }
            __syncthreads();
            if (warpRow == 0 && g == 0) {
                const int slot = 16 + I;
                #pragma unroll
                for (int ci = 0; ci < 8; ci++) {
                    const int cl = C0w + (ci >> 1) * 8 + tg * 2 + (ci & 1);
                    lse_merge(tm[ci], ts[ci], red[cl * 3 + 0], red[cl * 3 + 1]);
                    tp[ci] += red[cl * 3 + 2];
                    const int gr = J * TILE + cl;
                    g_pm[slot * N_TOT + gr] = tm[ci];
                    g_ps[slot * N_TOT + gr] = ts[ci];
                    g_pp[slot * N_TOT + gr] = tp[ci];
                }
            }
        } else {
            __syncthreads();
        }

        if (t + 2 < L) {
            load_tile(t & 1 ? sb + SM_B1 : sb + SM_B0, (J + 2) * TILE, tid);
            CP_COMMIT();
        }
    }

    // ---- row-partial writeout
    #pragma unroll
    for (int ri = 0; ri < 8; ri++) {
        #pragma unroll
        for (int off = 1; off < 4; off <<= 1) {
            float mo = __shfl_xor_sync(0xffffffffu, m[ri],  off);
            float so = __shfl_xor_sync(0xffffffffu, s[ri],  off);
            float po = __shfl_xor_sync(0xffffffffu, pv[ri], off);
            lse_merge(m[ri], s[ri], mo, so);
            pv[ri] += po;
        }
    }
    __syncthreads();
    float* redm = (float*)(smem + SM_B0);
    float* reds = redm + 512;
    float* redp = redm + 1024;
    if (tg == 0) {
        #pragma unroll
        for (int ri = 0; ri < 8; ri++) {
            const int rl = R0 + (ri >> 1) * 16 + (ri & 1) * 8 + g;
            redm[rl * 4 + warpCol] = m[ri];
            reds[rl * 4 + warpCol] = s[ri];
            redp[rl * 4 + warpCol] = pv[ri];
        }
    }
    __syncthreads();
    if (tid < TILE) {
        float M = redm[tid * 4 + 0], S = reds[tid * 4 + 0], P = redp[tid * 4 + 0];
        #pragma unroll
        for (int w = 1; w < 4; w++) {
            lse_merge(M, S, redm[tid * 4 + w], reds[tid * 4 + w]);
            P += redp[tid * 4 + w];
        }
        const int idx = mchunk * N_TOT + r0 + tid;
        g_pm[idx] = M; g_ps[idx] = S; g_pp[idx] = P;
    }
}

// ---------------------------------------------------------------------------
__global__ void infonce_reduce()
{
    const int r = blockIdx.x * 256 + threadIdx.x;   // 32 x 256 = 8192
    float M = -1e30f, S = 0.0f, P = 0.0f;
    #pragma unroll 8
    for (int k = 0; k < SLOTS; k++) {
        lse_merge(M, S, g_pm[k * N_TOT + r], g_ps[k * N_TOT + r]);
        P += g_pp[k * N_TOT + r];
    }
    S += ex2f(P - M);                  // positive's logits[:,0] copy
    float val = M + log2f(S) - P;      // row LSE - pos (log2 units)

    __shared__ double redd[256];
    redd[threadIdx.x] = (double)val;
    __syncthreads();
    #pragma unroll
    for (int off = 128; off > 0; off >>= 1) {
        if (threadIdx.x < off) redd[threadIdx.x] += redd[threadIdx.x + off];
        __syncthreads();
    }
    if (threadIdx.x == 0) atomicAdd(&g_acc, redd[0]);
}

__global__ void infonce_final(float* out)
{
    out[0] = (float)(g_acc * LN2 / (double)N_TOT);
}

// ---------------------------------------------------------------------------
extern "C" void kernel_launch(void* const* d_in, const int* in_sizes, int n_in,
                              void* d_out, int out_size)
{
    const float* zi = (const float*)d_in[0];
    const float* zj = (const float*)d_in[1];
    float* out = (float*)d_out;

    static bool attr_set = false;
    if (!attr_set) {
        cudaFuncSetAttribute(infonce_mma_kernel,
                             cudaFuncAttributeMaxDynamicSharedMemorySize, SMEM_BYTES);
        attr_set = true;
    }

    infonce_prep<<<2048, 256>>>(zi, zj);
    infonce_mma_kernel<<<NBLOCKS, THREADS, SMEM_BYTES>>>();
    infonce_reduce<<<32, 256>>>();
    infonce_final<<<1, 1>>>(out);
}

// round 8
// speedup vs baseline: 7.9116x; 1.0618x over previous
#include <cuda_runtime.h>
#include <cuda_bf16.h>
#include <cstdint>
#include <math.h>

// ============================================================================
// InfoNCE / NT-Xent loss via mma.sync bf16 m16n8k16 (RN-prerounded inputs),
// sim = sim^T: only upper-triangular 128x128 tiles (2080).
// Persistent balanced schedule: 296 CTAs (2/SM, one wave), each a contiguous
// range of 7-8 tiles from the linearized triangle; B double-buffer prefetched
// one full tile ahead; A reloaded only at row transitions.
// Partial slots per row: slot bid&15 (row segments), slot 16+I (col partials).
// Log2-domain softmax; positive's logits[:,0] copy added in the reducer.
// ============================================================================

#define N_TOT   8192
#define B_HALF  4096
#define TILE    128
#define THREADS 256
#define NCTA    296
#define NTILES  2080
#define SLOTS   80

#define C_L2E   14.4269504088896340736f   // (1/T)*log2(e)
#define LN2     0.69314718055994530942

#define LDB       272                      // bf16 tile row stride bytes
#define LDW       68                       // words per row
#define TILE_BYTES (TILE * LDB)            // 34816
#define SM_A      0
#define SM_B0     TILE_BYTES
#define SM_B1     (2 * TILE_BYTES)
#define SM_RED    (3 * TILE_BYTES)         // 6 KB reduce buffer
#define SMEM_BYTES (3 * TILE_BYTES + 6144) // 110592 -> 2 CTAs/SM

__device__ __nv_bfloat162 Zbf[N_TOT * 64];
__device__ float    g_pm[SLOTS * N_TOT];
__device__ float    g_ps[SLOTS * N_TOT];
__device__ float    g_pp[SLOTS * N_TOT];
__device__ double   g_acc;
__device__ unsigned g_done;

// ---------------------------------------------------------------------------
__device__ __forceinline__ uint32_t smem_u32(const void* p) {
    uint32_t a;
    asm("{ .reg .u64 t; cvta.to.shared.u64 t, %1; cvt.u32.u64 %0, t; }"
        : "=r"(a) : "l"(p));
    return a;
}
__device__ __forceinline__ float ex2f(float x) {
    float y; asm("ex2.approx.ftz.f32 %0, %1;" : "=f"(y) : "f"(x)); return y;
}
__device__ __forceinline__ void cp16(uint32_t dst, const void* src) {
    asm volatile("cp.async.cg.shared.global [%0], [%1], 16;" :: "r"(dst), "l"(src));
}
#define CP_COMMIT() asm volatile("cp.async.commit_group;" ::: "memory")
template <int N>
__device__ __forceinline__ void cp_wait() {
    asm volatile("cp.async.wait_group %0;" :: "n"(N) : "memory");
}
__device__ __forceinline__ void mma16(float& d0, float& d1, float& d2, float& d3,
                                      uint32_t a0, uint32_t a1, uint32_t a2, uint32_t a3,
                                      uint32_t b0, uint32_t b1) {
    asm volatile(
        "mma.sync.aligned.m16n8k16.row.col.f32.bf16.bf16.f32 "
        "{%0,%1,%2,%3}, {%4,%5,%6,%7}, {%8,%9}, {%0,%1,%2,%3};"
        : "+f"(d0), "+f"(d1), "+f"(d2), "+f"(d3)
        : "r"(a0), "r"(a1), "r"(a2), "r"(a3), "r"(b0), "r"(b1));
}
__device__ __forceinline__ void lse_merge(float& m1, float& s1, float m2, float s2) {
    float mn = fmaxf(m1, m2), ml = fminf(m1, m2);
    float shi = (m1 >= m2) ? s1 : s2;
    float slo = (m1 >= m2) ? s2 : s1;
    s1 = shi + slo * ex2f(ml - mn);
    m1 = mn;
}
__device__ __forceinline__ void load_tile(uint32_t sdst, int gRow0, int tid) {
    const char* src = (const char*)Zbf + (size_t)gRow0 * 256;
    #pragma unroll
    for (int it = 0; it < 8; it++) {
        int c = tid + it * THREADS;
        int row = c >> 4, q = c & 15;
        cp16(sdst + row * LDB + q * 16, src + row * 256 + q * 16);
    }
}

// ---------------------------------------------------------------------------
__global__ void infonce_prep(const float* __restrict__ zi,
                             const float* __restrict__ zj)
{
    const int i = blockIdx.x * 256 + threadIdx.x;   // 2048*256 = 524288
    {
        const int e = i * 2;
        const float2 v = (e < B_HALF * 128)
            ? *(const float2*)(zi + e)
            : *(const float2*)(zj + (e - B_HALF * 128));
        Zbf[i] = __floats2bfloat162_rn(v.x, v.y);
    }
    const int n = SLOTS * N_TOT;
    for (int k = i; k < n; k += 2048 * 256) {
        g_pm[k] = -1e30f; g_ps[k] = 0.0f; g_pp[k] = 0.0f;
    }
    if (i == 0) { g_acc = 0.0; g_done = 0u; }
}

// ---------------------------------------------------------------------------
__global__ __launch_bounds__(THREADS, 2)
void infonce_mma_kernel()
{
    extern __shared__ char smem[];
    const uint32_t sb = smem_u32(smem);
    const int tid = threadIdx.x, lane = tid & 31, wid = tid >> 5;
    const int g = lane >> 2, tg = lane & 3;
    const int warpRow = wid >> 2, warpCol = wid & 3;
    const int R0 = warpRow * 64, C0w = warpCol * 32;

    const int t0 = (int)(((long long)blockIdx.x * NTILES) / NCTA);
    const int t1 = (int)(((long long)(blockIdx.x + 1) * NTILES) / NCTA);
    const int slot = blockIdx.x & 15;

    // locate (I, J) of tile t0 in the row-major triangle
    int I = 0, base = 0;
    while (base + (64 - I) <= t0) { base += 64 - I; I++; }
    int J = I + (t0 - base);

    const uint32_t* Aw = (const uint32_t*)smem;
    const uint32_t* Bwbuf[2] = { (const uint32_t*)(smem + SM_B0),
                                 (const uint32_t*)(smem + SM_B1) };
    float* redm = (float*)(smem + SM_RED);          // 512 floats
    float* reds = redm + 512;
    float* redp = redm + 1024;

    load_tile(sb + SM_A,  I * TILE, tid);
    load_tile(sb + SM_B0, J * TILE, tid);
    CP_COMMIT();

    float m[8], s[8], pv[8];
    #pragma unroll
    for (int r = 0; r < 8; r++) { m[r] = -1e30f; s[r] = 0.0f; pv[r] = 0.0f; }

    for (int t = t0; t < t1; t++) {
        const int lt = t - t0;
        int In = I, Jn = J + 1;
        if (Jn == 64) { In = I + 1; Jn = In; }

        cp_wait<0>();
        __syncthreads();
        if (t + 1 < t1) {               // prefetch next B a full tile ahead
            load_tile((lt & 1) ? sb + SM_B0 : sb + SM_B1, Jn * TILE, tid);
            CP_COMMIT();
        }

        const uint32_t* Bw = Bwbuf[lt & 1];
        const int tileC0 = J * TILE + C0w;
        const int rowBase = I * TILE + R0;

        float acc[4][4][4];
        #pragma unroll
        for (int i = 0; i < 4; i++)
            #pragma unroll
            for (int j = 0; j < 4; j++)
                #pragma unroll
                for (int c = 0; c < 4; c++) acc[i][j][c] = 0.0f;

        #pragma unroll 4
        for (int ks = 0; ks < 8; ks++) {
            const int kw = ks * 8 + tg;
            uint32_t A0[4], A1[4], A2[4], A3[4];
            #pragma unroll
            for (int i = 0; i < 4; i++) {
                const uint32_t* ap = Aw + (R0 + i * 16 + g) * LDW + kw;
                A0[i] = ap[0];
                A2[i] = ap[4];
                A1[i] = ap[8 * LDW];
                A3[i] = ap[8 * LDW + 4];
            }
            uint32_t B0r[4], B1r[4];
            #pragma unroll
            for (int j = 0; j < 4; j++) {
                const uint32_t* bp = Bw + (C0w + j * 8 + g) * LDW + kw;
                B0r[j] = bp[0];
                B1r[j] = bp[4];
            }
            #pragma unroll
            for (int i = 0; i < 4; i++)
                #pragma unroll
                for (int j = 0; j < 4; j++)
                    mma16(acc[i][j][0], acc[i][j][1], acc[i][j][2], acc[i][j][3],
                          A0[i], A1[i], A2[i], A3[i], B0r[j], B1r[j]);
        }

        // ---- row-wise online LSE (rows of block I)
        #pragma unroll
        for (int i = 0; i < 4; i++) {
            #pragma unroll
            for (int h = 0; h < 2; h++) {
                const int ri = i * 2 + h;
                const int rowg = rowBase + i * 16 + h * 8 + g;
                const int prow = rowg ^ B_HALF;
                float f[8], rmax = -1e30f;
                #pragma unroll
                for (int j = 0; j < 4; j++) {
                    #pragma unroll
                    for (int qq = 0; qq < 2; qq++) {
                        const int colg = tileC0 + j * 8 + tg * 2 + qq;
                        float v = acc[i][j][h * 2 + qq] * C_L2E;
                        if (colg == rowg) v = -1e30f;
                        if (colg == prow) pv[ri] = v;
                        f[j * 2 + qq] = v;
                        rmax = fmaxf(rmax, v);
                    }
                }
                if (rmax > m[ri] - 27.0f) {
                    const float mn = fmaxf(m[ri], rmax);
                    float acc_s = s[ri] * ex2f(m[ri] - mn);
                    #pragma unroll
                    for (int x = 0; x < 8; x++) acc_s += ex2f(f[x] - mn);
                    m[ri] = mn; s[ri] = acc_s;
                }
            }
        }

        // ---- column-wise LSE partials (rows of block J) for off-diag tiles
        if (J > I) {
            float tm[8], ts[8], tp[8];
            #pragma unroll
            for (int j = 0; j < 4; j++) {
                #pragma unroll
                for (int qq = 0; qq < 2; qq++) {
                    const int ci = j * 2 + qq;
                    const int colg = tileC0 + j * 8 + tg * 2 + qq;
                    const int target = colg ^ B_HALF;
                    float mx = -1e30f;
                    #pragma unroll
                    for (int i = 0; i < 4; i++)
                        mx = fmaxf(mx, fmaxf(acc[i][j][qq], acc[i][j][2 + qq]));
                    mx *= C_L2E;
                    float ssum = 0.0f, pvv = 0.0f;
                    #pragma unroll
                    for (int i = 0; i < 4; i++) {
                        #pragma unroll
                        for (int h = 0; h < 2; h++) {
                            const float v = acc[i][j][h * 2 + qq] * C_L2E;
                            const int rowg = rowBase + i * 16 + h * 8 + g;
                            if (rowg == target) pvv = v;
                            ssum += ex2f(v - mx);
                        }
                    }
                    tm[ci] = mx; ts[ci] = ssum; tp[ci] = pvv;
                }
            }
            #pragma unroll
            for (int off = 4; off <= 16; off <<= 1) {
                #pragma unroll
                for (int ci = 0; ci < 8; ci++) {
                    float mo = __shfl_xor_sync(0xffffffffu, tm[ci], off);
                    float so = __shfl_xor_sync(0xffffffffu, ts[ci], off);
                    float po = __shfl_xor_sync(0xffffffffu, tp[ci], off);
                    lse_merge(tm[ci], ts[ci], mo, so);
                    tp[ci] += po;
                }
            }
            __syncthreads();
            if (warpRow == 1 && g == 0) {
                #pragma unroll
                for (int ci = 0; ci < 8; ci++) {
                    const int cl = C0w + (ci >> 1) * 8 + tg * 2 + (ci & 1);
                    redm[cl * 3 + 0] = tm[ci];
                    redm[cl * 3 + 1] = ts[ci];
                    redm[cl * 3 + 2] = tp[ci];
                }
            }
            __syncthreads();
            if (warpRow == 0 && g == 0) {
                const int cslot = 16 + I;
                #pragma unroll
                for (int ci = 0; ci < 8; ci++) {
                    const int cl = C0w + (ci >> 1) * 8 + tg * 2 + (ci & 1);
                    lse_merge(tm[ci], ts[ci], redm[cl * 3 + 0], redm[cl * 3 + 1]);
                    tp[ci] += redm[cl * 3 + 2];
                    const int gr = J * TILE + cl;
                    g_pm[cslot * N_TOT + gr] = tm[ci];
                    g_ps[cslot * N_TOT + gr] = ts[ci];
                    g_pp[cslot * N_TOT + gr] = tp[ci];
                }
            }
        }

        // ---- segment flush (row transition or final tile)
        const bool lastT = (t + 1 == t1);
        if (lastT || In != I) {
            #pragma unroll
            for (int ri = 0; ri < 8; ri++) {
                #pragma unroll
                for (int off = 1; off < 4; off <<= 1) {
                    float mo = __shfl_xor_sync(0xffffffffu, m[ri],  off);
                    float so = __shfl_xor_sync(0xffffffffu, s[ri],  off);
                    float po = __shfl_xor_sync(0xffffffffu, pv[ri], off);
                    lse_merge(m[ri], s[ri], mo, so);
                    pv[ri] += po;
                }
            }
            __syncthreads();      // also guarantees all A reads done
            if (tg == 0) {
                #pragma unroll
                for (int ri = 0; ri < 8; ri++) {
                    const int rl = R0 + (ri >> 1) * 16 + (ri & 1) * 8 + g;
                    redm[rl * 4 + warpCol] = m[ri];
                    reds[rl * 4 + warpCol] = s[ri];
                    redp[rl * 4 + warpCol] = pv[ri];
                }
            }
            __syncthreads();
            if (tid < TILE) {
                float M = redm[tid * 4 + 0], S = reds[tid * 4 + 0], P = redp[tid * 4 + 0];
                #pragma unroll
                for (int w = 1; w < 4; w++) {
                    lse_merge(M, S, redm[tid * 4 + w], reds[tid * 4 + w]);
                    P += redp[tid * 4 + w];
                }
                const int idx = slot * N_TOT + I * TILE + tid;
                g_pm[idx] = M; g_ps[idx] = S; g_pp[idx] = P;
            }
            if (!lastT) {
                __syncthreads();  // redm reads done before possible reuse
                #pragma unroll
                for (int r = 0; r < 8; r++) { m[r] = -1e30f; s[r] = 0.0f; pv[r] = 0.0f; }
                load_tile(sb + SM_A, In * TILE, tid);   // reload A for new row
                CP_COMMIT();
            }
        }

        I = In; J = Jn;
    }
}

// ---------------------------------------------------------------------------
// merge 80 slots per row, add positive's logits[:,0] copy, mean; last block
// writes the final scalar (counter-gated).
__global__ void infonce_reduce(float* out)
{
    const int r = blockIdx.x * 256 + threadIdx.x;   // 32 x 256 = 8192
    float M = -1e30f, S = 0.0f, P = 0.0f;
    #pragma unroll 8
    for (int k = 0; k < SLOTS; k++) {
        lse_merge(M, S, g_pm[k * N_TOT + r], g_ps[k * N_TOT + r]);
        P += g_pp[k * N_TOT + r];
    }
    S += ex2f(P - M);
    float val = M + log2f(S) - P;

    __shared__ double redd[256];
    redd[threadIdx.x] = (double)val;
    __syncthreads();
    #pragma unroll
    for (int off = 128; off > 0; off >>= 1) {
        if (threadIdx.x < off) redd[threadIdx.x] += redd[threadIdx.x + off];
        __syncthreads();
    }
    if (threadIdx.x == 0) {
        atomicAdd(&g_acc, redd[0]);
        __threadfence();
        unsigned done = atomicAdd(&g_done, 1u);
        if (done == 31u) {
            __threadfence();
            out[0] = (float)(g_acc * LN2 / (double)N_TOT);
        }
    }
}

// ---------------------------------------------------------------------------
extern "C" void kernel_launch(void* const* d_in, const int* in_sizes, int n_in,
                              void* d_out, int out_size)
{
    const float* zi = (const float*)d_in[0];
    const float* zj = (const float*)d_in[1];
    float* out = (float*)d_out;

    static bool attr_set = false;
    if (!attr_set) {
        cudaFuncSetAttribute(infonce_mma_kernel,
                             cudaFuncAttributeMaxDynamicSharedMemorySize, SMEM_BYTES);
        attr_set = true;
    }

    infonce_prep<<<2048, 256>>>(zi, zj);
    infonce_mma_kernel<<<NCTA, THREADS, SMEM_BYTES>>>();
    infonce_reduce<<<32, 256>>>(out);
}

// round 11
// speedup vs baseline: 8.4633x; 1.0697x over previous
#include <cuda_runtime.h>
#include <cuda_bf16.h>
#include <cstdint>
#include <math.h>

// ============================================================================
// InfoNCE / NT-Xent via mma.sync bf16 m16n8k16, sim = sim^T (upper-tri tiles).
// R8 structure (persistent 296 CTAs, balanced contiguous tile ranges, B
// double-buffer prefetch, col partials via smem reduction, 80 slots) with ONE
// change vs the 66.3us baseline: ldmatrix operand feed instead of scalar LDS.
// ============================================================================

#define N_TOT   8192
#define B_HALF  4096
#define TILE    128
#define THREADS 256
#define NCTA    296
#define NTILES  2080
#define SLOTS   80

#define C_L2E   14.4269504088896340736f   // (1/T)*log2(e)
#define LN2     0.69314718055994530942

#define LDB       272                      // bf16 tile row stride bytes
#define TILE_BYTES (TILE * LDB)            // 34816
#define SM_A      0
#define SM_B0     TILE_BYTES
#define SM_B1     (2 * TILE_BYTES)
#define SM_RED    (3 * TILE_BYTES)         // 6 KB reduce buffer
#define SMEM_BYTES (3 * TILE_BYTES + 6144) // 110592 -> 2 CTAs/SM

__device__ __nv_bfloat162 Zbf[N_TOT * 64];
__device__ float    g_pm[SLOTS * N_TOT];
__device__ float    g_ps[SLOTS * N_TOT];
__device__ float    g_pp[SLOTS * N_TOT];
__device__ double   g_acc;
__device__ unsigned g_done;

// ---------------------------------------------------------------------------
__device__ __forceinline__ uint32_t smem_u32(const void* p) {
    uint32_t a;
    asm("{ .reg .u64 t; cvta.to.shared.u64 t, %1; cvt.u32.u64 %0, t; }"
        : "=r"(a) : "l"(p));
    return a;
}
__device__ __forceinline__ float ex2f(float x) {
    float y; asm("ex2.approx.ftz.f32 %0, %1;" : "=f"(y) : "f"(x)); return y;
}
__device__ __forceinline__ void cp16(uint32_t dst, const void* src) {
    asm volatile("cp.async.cg.shared.global [%0], [%1], 16;" :: "r"(dst), "l"(src));
}
#define CP_COMMIT() asm volatile("cp.async.commit_group;" ::: "memory")
template <int N>
__device__ __forceinline__ void cp_wait() {
    asm volatile("cp.async.wait_group %0;" :: "n"(N) : "memory");
}
__device__ __forceinline__ void ldsm4(uint32_t& r0, uint32_t& r1,
                                      uint32_t& r2, uint32_t& r3, uint32_t a) {
    asm volatile("ldmatrix.sync.aligned.m8n8.x4.shared.b16 {%0,%1,%2,%3}, [%4];"
                 : "=r"(r0), "=r"(r1), "=r"(r2), "=r"(r3) : "r"(a));
}
__device__ __forceinline__ void ldsm2(uint32_t& r0, uint32_t& r1, uint32_t a) {
    asm volatile("ldmatrix.sync.aligned.m8n8.x2.shared.b16 {%0,%1}, [%2];"
                 : "=r"(r0), "=r"(r1) : "r"(a));
}
__device__ __forceinline__ void mma16(float& d0, float& d1, float& d2, float& d3,
                                      uint32_t a0, uint32_t a1, uint32_t a2, uint32_t a3,
                                      uint32_t b0, uint32_t b1) {
    asm volatile(
        "mma.sync.aligned.m16n8k16.row.col.f32.bf16.bf16.f32 "
        "{%0,%1,%2,%3}, {%4,%5,%6,%7}, {%8,%9}, {%0,%1,%2,%3};"
        : "+f"(d0), "+f"(d1), "+f"(d2), "+f"(d3)
        : "r"(a0), "r"(a1), "r"(a2), "r"(a3), "r"(b0), "r"(b1));
}
__device__ __forceinline__ void lse_merge(float& m1, float& s1, float m2, float s2) {
    float mn = fmaxf(m1, m2), ml = fminf(m1, m2);
    float shi = (m1 >= m2) ? s1 : s2;
    float slo = (m1 >= m2) ? s2 : s1;
    s1 = shi + slo * ex2f(ml - mn);
    m1 = mn;
}
__device__ __forceinline__ void load_tile(uint32_t sdst, int gRow0, int tid) {
    const char* src = (const char*)Zbf + (size_t)gRow0 * 256;
    #pragma unroll
    for (int it = 0; it < 8; it++) {
        int c = tid + it * THREADS;
        int row = c >> 4, q = c & 15;
        cp16(sdst + row * LDB + q * 16, src + row * 256 + q * 16);
    }
}

// ---------------------------------------------------------------------------
__global__ void infonce_prep(const float* __restrict__ zi,
                             const float* __restrict__ zj)
{
    const int i = blockIdx.x * 256 + threadIdx.x;   // 2048*256 = 524288
    {
        const int e = i * 2;
        const float2 v = (e < B_HALF * 128)
            ? *(const float2*)(zi + e)
            : *(const float2*)(zj + (e - B_HALF * 128));
        Zbf[i] = __floats2bfloat162_rn(v.x, v.y);
    }
    const int n = SLOTS * N_TOT;
    for (int k = i; k < n; k += 2048 * 256) {
        g_pm[k] = -1e30f; g_ps[k] = 0.0f; g_pp[k] = 0.0f;
    }
    if (i == 0) { g_acc = 0.0; g_done = 0u; }
}

// ---------------------------------------------------------------------------
__global__ __launch_bounds__(THREADS, 2)
void infonce_mma_kernel()
{
    extern __shared__ char smem[];
    const uint32_t sb = smem_u32(smem);
    const int tid = threadIdx.x, lane = tid & 31, wid = tid >> 5;
    const int g = lane >> 2, tg = lane & 3;
    const int warpRow = wid >> 2, warpCol = wid & 3;
    const int R0 = warpRow * 64, C0w = warpCol * 32;

    const int t0 = (int)(((long long)blockIdx.x * NTILES) / NCTA);
    const int t1 = (int)(((long long)(blockIdx.x + 1) * NTILES) / NCTA);
    const int slot = blockIdx.x & 15;

    int I = 0, base = 0;
    while (base + (64 - I) <= t0) { base += 64 - I; I++; }
    int J = I + (t0 - base);

    float* redm = (float*)(smem + SM_RED);
    float* reds = redm + 512;
    float* redp = redm + 1024;

    // ldmatrix per-lane addresses
    // A x4: lanes 0-15 -> rows (lane&15), k-bytes 0-15; lanes 16-31 -> +16B
    uint32_t aAddr[4], bOff[4];
    #pragma unroll
    for (int i = 0; i < 4; i++)
        aAddr[i] = sb + SM_A + (R0 + i * 16 + (lane & 15)) * LDB + (lane >> 4) * 16;
    // B x2: lanes 0-7 -> rows(n) (lane&7), k 0-7; lanes 8-15 -> +16B
    #pragma unroll
    for (int j = 0; j < 4; j++)
        bOff[j] = (C0w + j * 8 + (lane & 7)) * LDB + ((lane >> 3) & 1) * 16;

    load_tile(sb + SM_A,  I * TILE, tid);
    load_tile(sb + SM_B0, J * TILE, tid);
    CP_COMMIT();

    float m[8], s[8], pv[8];
    #pragma unroll
    for (int r = 0; r < 8; r++) { m[r] = -1e30f; s[r] = 0.0f; pv[r] = 0.0f; }

    for (int t = t0; t < t1; t++) {
        const int lt = t - t0;
        int In = I, Jn = J + 1;
        if (Jn == 64) { In = I + 1; Jn = In; }

        cp_wait<0>();
        __syncthreads();
        if (t + 1 < t1) {               // prefetch next B a full tile ahead
            load_tile((lt & 1) ? sb + SM_B0 : sb + SM_B1, Jn * TILE, tid);
            CP_COMMIT();
        }

        const uint32_t bBase = sb + ((lt & 1) ? SM_B1 : SM_B0);
        const int tileC0 = J * TILE + C0w;
        const int rowBase = I * TILE + R0;

        float acc[4][4][4];
        #pragma unroll
        for (int i = 0; i < 4; i++)
            #pragma unroll
            for (int j = 0; j < 4; j++)
                #pragma unroll
                for (int c = 0; c < 4; c++) acc[i][j][c] = 0.0f;

        #pragma unroll 4
        for (int ks = 0; ks < 8; ks++) {
            const uint32_t ko = ks * 32;        // 16 bf16 per k-step
            uint32_t A0[4], A1[4], A2[4], A3[4];
            #pragma unroll
            for (int i = 0; i < 4; i++)
                ldsm4(A0[i], A1[i], A2[i], A3[i], aAddr[i] + ko);
            uint32_t B0r[4], B1r[4];
            #pragma unroll
            for (int j = 0; j < 4; j++)
                ldsm2(B0r[j], B1r[j], bBase + bOff[j] + ko);
            #pragma unroll
            for (int i = 0; i < 4; i++)
                #pragma unroll
                for (int j = 0; j < 4; j++)
                    mma16(acc[i][j][0], acc[i][j][1], acc[i][j][2], acc[i][j][3],
                          A0[i], A1[i], A2[i], A3[i], B0r[j], B1r[j]);
        }

        // ---- row-wise online LSE (rows of block I)  [identical to R8]
        #pragma unroll
        for (int i = 0; i < 4; i++) {
            #pragma unroll
            for (int h = 0; h < 2; h++) {
                const int ri = i * 2 + h;
                const int rowg = rowBase + i * 16 + h * 8 + g;
                const int prow = rowg ^ B_HALF;
                float f[8], rmax = -1e30f;
                #pragma unroll
                for (int j = 0; j < 4; j++) {
                    #pragma unroll
                    for (int qq = 0; qq < 2; qq++) {
                        const int colg = tileC0 + j * 8 + tg * 2 + qq;
                        float v = acc[i][j][h * 2 + qq] * C_L2E;
                        if (colg == rowg) v = -1e30f;
                        if (colg == prow) pv[ri] = v;
                        f[j * 2 + qq] = v;
                        rmax = fmaxf(rmax, v);
                    }
                }
                if (rmax > m[ri] - 27.0f) {
                    const float mn = fmaxf(m[ri], rmax);
                    float acc_s = s[ri] * ex2f(m[ri] - mn);
                    #pragma unroll
                    for (int x = 0; x < 8; x++) acc_s += ex2f(f[x] - mn);
                    m[ri] = mn; s[ri] = acc_s;
                }
            }
        }

        // ---- column-wise LSE partials (rows of block J)  [identical to R8]
        if (J > I) {
            float tm[8], ts[8], tp[8];
            #pragma unroll
            for (int j = 0; j < 4; j++) {
                #pragma unroll
                for (int qq = 0; qq < 2; qq++) {
                    const int ci = j * 2 + qq;
                    const int colg = tileC0 + j * 8 + tg * 2 + qq;
                    const int target = colg ^ B_HALF;
                    float mx = -1e30f;
                    #pragma unroll
                    for (int i = 0; i < 4; i++)
                        mx = fmaxf(mx, fmaxf(acc[i][j][qq], acc[i][j][2 + qq]));
                    mx *= C_L2E;
                    float ssum = 0.0f, pvv = 0.0f;
                    #pragma unroll
                    for (int i = 0; i < 4; i++) {
                        #pragma unroll
                        for (int h = 0; h < 2; h++) {
                            const float v = acc[i][j][h * 2 + qq] * C_L2E;
                            const int rowg = rowBase + i * 16 + h * 8 + g;
                            if (rowg == target) pvv = v;
                            ssum += ex2f(v - mx);
                        }
                    }
                    tm[ci] = mx; ts[ci] = ssum; tp[ci] = pvv;
                }
            }
            #pragma unroll
            for (int off = 4; off <= 16; off <<= 1) {
                #pragma unroll
                for (int ci = 0; ci < 8; ci++) {
                    float mo = __shfl_xor_sync(0xffffffffu, tm[ci], off);
                    float so = __shfl_xor_sync(0xffffffffu, ts[ci], off);
                    float po = __shfl_xor_sync(0xffffffffu, tp[ci], off);
                    lse_merge(tm[ci], ts[ci], mo, so);
                    tp[ci] += po;
                }
            }
            __syncthreads();
            if (warpRow == 1 && g == 0) {
                #pragma unroll
                for (int ci = 0; ci < 8; ci++) {
                    const int cl = C0w + (ci >> 1) * 8 + tg * 2 + (ci & 1);
                    redm[cl * 3 + 0] = tm[ci];
                    redm[cl * 3 + 1] = ts[ci];
                    redm[cl * 3 + 2] = tp[ci];
                }
            }
            __syncthreads();
            if (warpRow == 0 && g == 0) {
                const int cslot = 16 + I;
                #pragma unroll
                for (int ci = 0; ci < 8; ci++) {
                    const int cl = C0w + (ci >> 1) * 8 + tg * 2 + (ci & 1);
                    lse_merge(tm[ci], ts[ci], redm[cl * 3 + 0], redm[cl * 3 + 1]);
                    tp[ci] += redm[cl * 3 + 2];
                    const int gr = J * TILE + cl;
                    g_pm[cslot * N_TOT + gr] = tm[ci];
                    g_ps[cslot * N_TOT + gr] = ts[ci];
                    g_pp[cslot * N_TOT + gr] = tp[ci];
                }
            }
        }

        // ---- segment flush (row transition or final tile)  [identical to R8]
        const bool lastT = (t + 1 == t1);
        if (lastT || In != I) {
            #pragma unroll
            for (int ri = 0; ri < 8; ri++) {
                #pragma unroll
                for (int off = 1; off < 4; off <<= 1) {
                    float mo = __shfl_xor_sync(0xffffffffu, m[ri],  off);
                    float so = __shfl_xor_sync(0xffffffffu, s[ri],  off);
                    float po = __shfl_xor_sync(0xffffffffu, pv[ri], off);
                    lse_merge(m[ri], s[ri], mo, so);
                    pv[ri] += po;
                }
            }
            __syncthreads();
            if (tg == 0) {
                #pragma unroll
                for (int ri = 0; ri < 8; ri++) {
                    const int rl = R0 + (ri >> 1) * 16 + (ri & 1) * 8 + g;
                    redm[rl * 4 + warpCol] = m[ri];
                    reds[rl * 4 + warpCol] = s[ri];
                    redp[rl * 4 + warpCol] = pv[ri];
                }
            }
            __syncthreads();
            if (tid < TILE) {
                float M = redm[tid * 4 + 0], S = reds[tid * 4 + 0], P = redp[tid * 4 + 0];
                #pragma unroll
                for (int wq = 1; wq < 4; wq++) {
                    lse_merge(M, S, redm[tid * 4 + wq], reds[tid * 4 + wq]);
                    P += redp[tid * 4 + wq];
                }
                const int idx = slot * N_TOT + I * TILE + tid;
                g_pm[idx] = M; g_ps[idx] = S; g_pp[idx] = P;
            }
            if (!lastT) {
                __syncthreads();
                #pragma unroll
                for (int r = 0; r < 8; r++) { m[r] = -1e30f; s[r] = 0.0f; pv[r] = 0.0f; }
                load_tile(sb + SM_A, In * TILE, tid);
                CP_COMMIT();
            }
        }

        I = In; J = Jn;
    }
}

// ---------------------------------------------------------------------------
__global__ void infonce_reduce(float* out)
{
    const int r = blockIdx.x * 256 + threadIdx.x;   // 32 x 256 = 8192
    float M = -1e30f, S = 0.0f, P = 0.0f;
    #pragma unroll 8
    for (int k = 0; k < SLOTS; k++) {
        lse_merge(M, S, g_pm[k * N_TOT + r], g_ps[k * N_TOT + r]);
        P += g_pp[k * N_TOT + r];
    }
    S += ex2f(P - M);
    float val = M + log2f(S) - P;

    __shared__ double redd[256];
    redd[threadIdx.x] = (double)val;
    __syncthreads();
    #pragma unroll
    for (int off = 128; off > 0; off >>= 1) {
        if (threadIdx.x < off) redd[threadIdx.x] += redd[threadIdx.x + off];
        __syncthreads();
    }
    if (threadIdx.x == 0) {
        atomicAdd(&g_acc, redd[0]);
        __threadfence();
        unsigned done = atomicAdd(&g_done, 1u);
        if (done == 31u) {
            __threadfence();
            out[0] = (float)(g_acc * LN2 / (double)N_TOT);
        }
    }
}

// ---------------------------------------------------------------------------
extern "C" void kernel_launch(void* const* d_in, const int* in_sizes, int n_in,
                              void* d_out, int out_size)
{
    const float* zi = (const float*)d_in[0];
    const float* zj = (const float*)d_in[1];
    float* out = (float*)d_out;

    static bool attr_set = false;
    if (!attr_set) {
        cudaFuncSetAttribute(infonce_mma_kernel,
                             cudaFuncAttributeMaxDynamicSharedMemorySize, SMEM_BYTES);
        attr_set = true;
    }

    infonce_prep<<<2048, 256>>>(zi, zj);
    infonce_mma_kernel<<<NCTA, THREADS, SMEM_BYTES>>>();
    infonce_reduce<<<32, 256>>>(out);
}